// round 5
// baseline (speedup 1.0000x reference)
#include <cuda_runtime.h>
#include <cuda_bf16.h>

// FrozenBNBStableEmbedding: blockwise-int8 dequant embedding gather + LayerNorm.
//
// Inputs (metadata order):
//   0: x        int32  [8, 2048]           token ids (16384) — jnp.int64 degrades
//                                          to int32 without JAX x64 mode
//   1: weight_i8 int32 [50304, 1024]       code indices 0..255
//   2: absmax   float32 [12576]            per-4096-elem block scale == per (row>>2)
//   3: code     float32 [256]              dequant codebook
//   4: ln_weight float32 [1024]
//   5: ln_bias   float32 [1024]
// Output: float32 [8, 2048, 1024]
//
// One CTA per token. 256 threads x 4 elems = 1024 = D.

#define D 1024
#define V 50304
#define EPS 1e-5f

__global__ __launch_bounds__(256, 8)
void frozen_bnb_emb_ln_kernel(const int* __restrict__ x,
                              const int* __restrict__ weight_i8,
                              const float* __restrict__ absmax,
                              const float* __restrict__ code,
                              const float* __restrict__ ln_weight,
                              const float* __restrict__ ln_bias,
                              float* __restrict__ out)
{
    __shared__ float s_code[256];
    __shared__ float s_part[16];   // [0..7]=sum partials, [8..15]=sumsq partials
    __shared__ float s_stats[2];   // mean, rstd

    const int tid  = threadIdx.x;
    const int warp = tid >> 5;
    const int lane = tid & 31;
    const int tok  = blockIdx.x;

    // Stage codebook in shared (exactly 256 threads)
    s_code[tid] = code[tid];

    int row = __ldg(&x[tok]);
    // Safety clamp: never fault even on unexpected index values.
    row = min(max(row, 0), V - 1);
    const float scale = __ldg(&absmax[row >> 2]);

    __syncthreads();

    // Coalesced int4 load of 4 codes per thread (one full 4 KB row per CTA)
    const int4* wrow = reinterpret_cast<const int4*>(weight_i8 + (long long)row * D);
    int4 c = __ldg(&wrow[tid]);

    float v0 = s_code[c.x & 255] * scale;
    float v1 = s_code[c.y & 255] * scale;
    float v2 = s_code[c.z & 255] * scale;
    float v3 = s_code[c.w & 255] * scale;

    float s  = v0 + v1 + v2 + v3;
    float sq = v0 * v0 + v1 * v1 + v2 * v2 + v3 * v3;

    // Warp reduction
    #pragma unroll
    for (int off = 16; off > 0; off >>= 1) {
        s  += __shfl_down_sync(0xFFFFFFFFu, s,  off);
        sq += __shfl_down_sync(0xFFFFFFFFu, sq, off);
    }
    if (lane == 0) {
        s_part[warp]     = s;
        s_part[8 + warp] = sq;
    }
    __syncthreads();

    if (warp == 0) {
        float ps  = (lane < 8) ? s_part[lane]     : 0.0f;
        float psq = (lane < 8) ? s_part[8 + lane] : 0.0f;
        #pragma unroll
        for (int off = 4; off > 0; off >>= 1) {
            ps  += __shfl_down_sync(0xFFFFFFFFu, ps,  off);
            psq += __shfl_down_sync(0xFFFFFFFFu, psq, off);
        }
        if (lane == 0) {
            float mean = ps * (1.0f / D);
            float var  = psq * (1.0f / D) - mean * mean;
            s_stats[0] = mean;
            s_stats[1] = rsqrtf(var + EPS);
        }
    }
    __syncthreads();

    const float mean = s_stats[0];
    const float rstd = s_stats[1];

    const float4 w4 = __ldg(reinterpret_cast<const float4*>(ln_weight) + tid);
    const float4 b4 = __ldg(reinterpret_cast<const float4*>(ln_bias) + tid);

    float4 o;
    o.x = (v0 - mean) * rstd * w4.x + b4.x;
    o.y = (v1 - mean) * rstd * w4.y + b4.y;
    o.z = (v2 - mean) * rstd * w4.z + b4.z;
    o.w = (v3 - mean) * rstd * w4.w + b4.w;

    reinterpret_cast<float4*>(out + (long long)tok * D)[tid] = o;
}

extern "C" void kernel_launch(void* const* d_in, const int* in_sizes, int n_in,
                              void* d_out, int out_size)
{
    const int*   x      = (const int*)d_in[0];
    const int*   w_i8   = (const int*)d_in[1];
    const float* absmax = (const float*)d_in[2];
    const float* code   = (const float*)d_in[3];
    const float* ln_w   = (const float*)d_in[4];
    const float* ln_b   = (const float*)d_in[5];
    float*       out    = (float*)d_out;

    const int n_tokens = in_sizes[0];   // 8*2048 = 16384

    frozen_bnb_emb_ln_kernel<<<n_tokens, 256>>>(x, w_i8, absmax, code, ln_w, ln_b, out);
}

// round 8
// speedup vs baseline: 1.0073x; 1.0073x over previous
#include <cuda_runtime.h>
#include <cuda_bf16.h>

// FrozenBNBStableEmbedding: blockwise-int8 dequant embedding gather + LayerNorm.
//
// Inputs (metadata order):
//   0: x         int32  [8, 2048]    token ids (16384)
//   1: weight_i8 int32  [50304,1024] code indices 0..255
//   2: absmax    f32    [12576]      per-4096-elem block scale == per (row>>2)
//   3: code      f32    [256]        dequant codebook
//   4: ln_weight f32    [1024]
//   5: ln_bias   f32    [1024]
// Output: f32 [8, 2048, 1024]
//
// 16 tokens per CTA, 256 threads, 4 elems/thread. Codebook replicated 32x in
// shared for bank-conflict-free lookups; ln params register-resident; next
// token's gather prefetched across the block reduction.

#define D 1024
#define V 50304
#define EPS 1e-5f
#define TOK_PER_CTA 16

__global__ __launch_bounds__(256, 6)
void frozen_bnb_emb_ln_kernel(const int* __restrict__ x,
                              const int* __restrict__ weight_i8,
                              const float* __restrict__ absmax,
                              const float* __restrict__ code,
                              const float* __restrict__ ln_weight,
                              const float* __restrict__ ln_bias,
                              float* __restrict__ out,
                              int n_tokens)
{
    __shared__ float s_rep[256 * 32];   // s_rep[idx*32 + lane] == code[idx]
    __shared__ float s_part[16];        // [0..7]=sum, [8..15]=sumsq
    __shared__ float s_stats[2];        // mean, rstd

    const int tid  = threadIdx.x;
    const int warp = tid >> 5;
    const int lane = tid & 31;

    // ---- Fill replicated codebook, conflict-free (swizzled write order) ----
    {
        const float cv = __ldg(&code[tid]);
        float* row = &s_rep[tid * 32];
        #pragma unroll
        for (int k = 0; k < 32; k++) {
            row[(lane + k) & 31] = cv;   // bank = (lane+k)&31, distinct per lane
        }
    }

    // ---- LayerNorm params: register-resident for all tokens ----
    const float4 w4 = __ldg(reinterpret_cast<const float4*>(ln_weight) + tid);
    const float4 b4 = __ldg(reinterpret_cast<const float4*>(ln_bias) + tid);

    const int tok_base = blockIdx.x * TOK_PER_CTA;

    __syncthreads();

    // ---- Prefetch token 0 gather ----
    int   row0 = min(max(__ldg(&x[tok_base]), 0), V - 1);
    float scale = __ldg(&absmax[row0 >> 2]);
    int4  c = __ldg(reinterpret_cast<const int4*>(weight_i8 + (long long)row0 * D) + tid);

    for (int t = 0; t < TOK_PER_CTA; t++) {
        const int tok = tok_base + t;

        // Prefetch next token's gather before the reductions (overlap latency)
        int4  cn;
        float scale_n = 0.0f;
        if (t + 1 < TOK_PER_CTA && tok + 1 < n_tokens) {
            int rn = min(max(__ldg(&x[tok + 1]), 0), V - 1);
            scale_n = __ldg(&absmax[rn >> 2]);
            cn = __ldg(reinterpret_cast<const int4*>(weight_i8 + (long long)rn * D) + tid);
        }

        // Conflict-free dequant lookups (bank == lane always)
        float v0 = s_rep[(c.x & 255) * 32 + lane] * scale;
        float v1 = s_rep[(c.y & 255) * 32 + lane] * scale;
        float v2 = s_rep[(c.z & 255) * 32 + lane] * scale;
        float v3 = s_rep[(c.w & 255) * 32 + lane] * scale;

        float s  = v0 + v1 + v2 + v3;
        float sq = v0 * v0 + v1 * v1 + v2 * v2 + v3 * v3;

        #pragma unroll
        for (int off = 16; off > 0; off >>= 1) {
            s  += __shfl_down_sync(0xFFFFFFFFu, s,  off);
            sq += __shfl_down_sync(0xFFFFFFFFu, sq, off);
        }
        if (lane == 0) {
            s_part[warp]     = s;
            s_part[8 + warp] = sq;
        }
        __syncthreads();

        if (warp == 0) {
            float ps  = (lane < 8) ? s_part[lane]     : 0.0f;
            float psq = (lane < 8) ? s_part[8 + lane] : 0.0f;
            #pragma unroll
            for (int off = 4; off > 0; off >>= 1) {
                ps  += __shfl_down_sync(0xFFFFFFFFu, ps,  off);
                psq += __shfl_down_sync(0xFFFFFFFFu, psq, off);
            }
            if (lane == 0) {
                float mean = ps * (1.0f / D);
                float var  = psq * (1.0f / D) - mean * mean;
                s_stats[0] = mean;
                s_stats[1] = rsqrtf(var + EPS);
            }
        }
        __syncthreads();

        const float mean = s_stats[0];
        const float rstd = s_stats[1];

        float4 o;
        o.x = (v0 - mean) * rstd * w4.x + b4.x;
        o.y = (v1 - mean) * rstd * w4.y + b4.y;
        o.z = (v2 - mean) * rstd * w4.z + b4.z;
        o.w = (v3 - mean) * rstd * w4.w + b4.w;

        reinterpret_cast<float4*>(out + (long long)tok * D)[tid] = o;

        c = cn;
        scale = scale_n;
        // NOTE: no extra sync needed — iter t+1's s_part/s_stats writes occur
        // only after its own __syncthreads barriers, ordered after all iter-t
        // reads of s_part/s_stats.
    }
}

extern "C" void kernel_launch(void* const* d_in, const int* in_sizes, int n_in,
                              void* d_out, int out_size)
{
    const int*   x      = (const int*)d_in[0];
    const int*   w_i8   = (const int*)d_in[1];
    const float* absmax = (const float*)d_in[2];
    const float* code   = (const float*)d_in[3];
    const float* ln_w   = (const float*)d_in[4];
    const float* ln_b   = (const float*)d_in[5];
    float*       out    = (float*)d_out;

    const int n_tokens = in_sizes[0];   // 16384
    const int grid = (n_tokens + TOK_PER_CTA - 1) / TOK_PER_CTA;  // 1024

    frozen_bnb_emb_ln_kernel<<<grid, 256>>>(x, w_i8, absmax, code, ln_w, ln_b, out, n_tokens);
}

// round 11
// speedup vs baseline: 1.2994x; 1.2901x over previous
#include <cuda_runtime.h>
#include <cuda_bf16.h>

// FrozenBNBStableEmbedding: blockwise-int8 dequant embedding gather + LayerNorm.
//
// Inputs (metadata order):
//   0: x         int32  [8, 2048]    token ids (16384)
//   1: weight_i8 int32  [50304,1024] code indices 0..255
//   2: absmax    f32    [12576]      per-4096-elem block scale == per (row>>2)
//   3: code      f32    [256]        dequant codebook
//   4: ln_weight f32    [1024]
//   5: ln_bias   f32    [1024]
// Output: f32 [8, 2048, 1024]
//
// WARP-PER-TOKEN: 32 lanes x 32 elems = D. No block barriers in the main loop;
// LayerNorm stats via warp shfl_xor only. 8 int4 gathers per lane issued as a
// burst -> 8x the memory-level parallelism of the block-per-token version.
// Codebook replicated 32x in shared (bank == lane, conflict-free).

#define D 1024
#define V 50304
#define EPS 1e-5f
#define T_PER_WARP 2
#define WARPS_PER_CTA 8

__global__ __launch_bounds__(256)
void frozen_bnb_emb_ln_kernel(const int* __restrict__ x,
                              const int* __restrict__ weight_i8,
                              const float* __restrict__ absmax,
                              const float* __restrict__ code,
                              const float* __restrict__ ln_weight,
                              const float* __restrict__ ln_bias,
                              float* __restrict__ out,
                              int n_tokens)
{
    __shared__ float  s_rep[256 * 32];   // s_rep[idx*32 + lane] == code[idx]
    __shared__ float4 s_w[256];          // ln_weight as float4
    __shared__ float4 s_b[256];          // ln_bias as float4

    const int tid  = threadIdx.x;
    const int warp = tid >> 5;
    const int lane = tid & 31;

    // ---- One-time staging (only sync in the kernel) ----
    {
        const float cv = __ldg(&code[tid]);
        float* row = &s_rep[tid * 32];
        #pragma unroll
        for (int k = 0; k < 32; k++)
            row[(lane + k) & 31] = cv;           // distinct bank per lane
        s_w[tid] = __ldg(reinterpret_cast<const float4*>(ln_weight) + tid);
        s_b[tid] = __ldg(reinterpret_cast<const float4*>(ln_bias) + tid);
    }
    __syncthreads();

    const int gwarp = blockIdx.x * WARPS_PER_CTA + warp;
    const int tok0  = gwarp * T_PER_WARP;
    if (tok0 >= n_tokens) return;

    // ---- Prefetch token 0: 8 int4 gathers issued back-to-back (MLP=8) ----
    int4  c[8];
    float scale;
    {
        int row = min(max(__ldg(&x[tok0]), 0), V - 1);
        scale = __ldg(&absmax[row >> 2]);
        const int4* wr = reinterpret_cast<const int4*>(weight_i8 + (long long)row * D);
        #pragma unroll
        for (int j = 0; j < 8; j++)
            c[j] = __ldg(wr + j * 32 + lane);
    }

    #pragma unroll
    for (int t = 0; t < T_PER_WARP; t++) {
        const int tok = tok0 + t;
        if (tok >= n_tokens) return;

        // ---- Dequant 32 values; accumulate sum / sumsq ----
        float v[32];
        float s = 0.0f, sq = 0.0f;
        #pragma unroll
        for (int j = 0; j < 8; j++) {
            float a0 = s_rep[(c[j].x & 255) * 32 + lane] * scale;
            float a1 = s_rep[(c[j].y & 255) * 32 + lane] * scale;
            float a2 = s_rep[(c[j].z & 255) * 32 + lane] * scale;
            float a3 = s_rep[(c[j].w & 255) * 32 + lane] * scale;
            v[4*j+0] = a0; v[4*j+1] = a1; v[4*j+2] = a2; v[4*j+3] = a3;
            s  += a0 + a1 + a2 + a3;
            sq += a0*a0 + a1*a1 + a2*a2 + a3*a3;
        }

        // ---- Prefetch next token's gather (overlaps reduce + stores) ----
        if (t + 1 < T_PER_WARP && tok + 1 < n_tokens) {
            int rn = min(max(__ldg(&x[tok + 1]), 0), V - 1);
            scale = __ldg(&absmax[rn >> 2]);
            const int4* wr = reinterpret_cast<const int4*>(weight_i8 + (long long)rn * D);
            #pragma unroll
            for (int j = 0; j < 8; j++)
                c[j] = __ldg(wr + j * 32 + lane);
        }

        // ---- Warp-only LayerNorm stats (no barriers) ----
        #pragma unroll
        for (int off = 16; off > 0; off >>= 1) {
            s  += __shfl_xor_sync(0xFFFFFFFFu, s,  off);
            sq += __shfl_xor_sync(0xFFFFFFFFu, sq, off);
        }
        const float mean = s * (1.0f / D);
        const float var  = sq * (1.0f / D) - mean * mean;
        const float rstd = rsqrtf(var + EPS);

        // ---- Affine + store (coalesced 512B per j) ----
        float4* orow = reinterpret_cast<float4*>(out + (long long)tok * D);
        #pragma unroll
        for (int j = 0; j < 8; j++) {
            const float4 w4 = s_w[j * 32 + lane];
            const float4 b4 = s_b[j * 32 + lane];
            float4 o;
            o.x = (v[4*j+0] - mean) * rstd * w4.x + b4.x;
            o.y = (v[4*j+1] - mean) * rstd * w4.y + b4.y;
            o.z = (v[4*j+2] - mean) * rstd * w4.z + b4.z;
            o.w = (v[4*j+3] - mean) * rstd * w4.w + b4.w;
            orow[j * 32 + lane] = o;
        }
    }
}

extern "C" void kernel_launch(void* const* d_in, const int* in_sizes, int n_in,
                              void* d_out, int out_size)
{
    const int*   x      = (const int*)d_in[0];
    const int*   w_i8   = (const int*)d_in[1];
    const float* absmax = (const float*)d_in[2];
    const float* code   = (const float*)d_in[3];
    const float* ln_w   = (const float*)d_in[4];
    const float* ln_b   = (const float*)d_in[5];
    float*       out    = (float*)d_out;

    const int n_tokens = in_sizes[0];   // 16384
    const int toks_per_cta = WARPS_PER_CTA * T_PER_WARP;   // 16
    const int grid = (n_tokens + toks_per_cta - 1) / toks_per_cta;  // 1024

    frozen_bnb_emb_ln_kernel<<<grid, 256>>>(x, w_i8, absmax, code, ln_w, ln_b, out, n_tokens);
}